// round 1
// baseline (speedup 1.0000x reference)
#include <cuda_runtime.h>
#include <cuda_bf16.h>
#include <math.h>

// Problem constants
#define B_     8
#define NQ_    1024
#define NK_    1024
#define DIM_   512
#define H_     8
#define HD_    64
#define MROWS  (B_ * NQ_)     // 8192
#define SCALE_ 0.04419417382415922f   // 1/sqrt(512)

// ---------------- scratch (device globals: allowed) ----------------
__device__ float g_Qp[MROWS * DIM_];
__device__ float g_Kp[MROWS * DIM_];
__device__ float g_Vp[MROWS * DIM_];
__device__ float g_O [MROWS * DIM_];
__device__ float g_O2[MROWS * DIM_];

// ---------------- SGEMM: C[M,512] = A[M,512] @ W[512,512] (+bias, opt. res+relu) ----------------
// BM=128 BN=128 BK=8, 256 threads, 8x8 per thread.
// MODE 0: C = acc + bias
// MODE 1: C = res + max(acc + bias, 0)
template <int MODE>
__global__ __launch_bounds__(256) void gemm512(const float* __restrict__ A,
                                               const float* __restrict__ W,
                                               const float* __restrict__ bias,
                                               const float* __restrict__ res,
                                               float* __restrict__ C) {
    __shared__ float As[8][128];
    __shared__ float Bs[8][128];

    const int tid = threadIdx.x;
    const int tx = tid & 15;          // 0..15 (n)
    const int ty = tid >> 4;          // 0..15 (m)
    const int mBase = blockIdx.y * 128;
    const int nBase = blockIdx.x * 128;

    const int arow = tid >> 1;        // 0..127
    const int acol = (tid & 1) * 4;   // 0 or 4
    const int brow = tid >> 5;        // 0..7
    const int bcol = (tid & 31) * 4;  // 0..124

    float acc[8][8];
#pragma unroll
    for (int i = 0; i < 8; i++)
#pragma unroll
        for (int j = 0; j < 8; j++) acc[i][j] = 0.f;

    const float* Aptr = A + (size_t)mBase * DIM_;

    for (int k0 = 0; k0 < DIM_; k0 += 8) {
        float4 av = *(const float4*)&Aptr[(size_t)arow * DIM_ + k0 + acol];
        As[acol + 0][arow] = av.x;
        As[acol + 1][arow] = av.y;
        As[acol + 2][arow] = av.z;
        As[acol + 3][arow] = av.w;
        *(float4*)&Bs[brow][bcol] =
            *(const float4*)&W[(size_t)(k0 + brow) * DIM_ + nBase + bcol];
        __syncthreads();

#pragma unroll
        for (int k = 0; k < 8; k++) {
            float a[8], b[8];
            float4 a0 = *(float4*)&As[k][ty * 8];
            float4 a1 = *(float4*)&As[k][ty * 8 + 4];
            a[0]=a0.x; a[1]=a0.y; a[2]=a0.z; a[3]=a0.w;
            a[4]=a1.x; a[5]=a1.y; a[6]=a1.z; a[7]=a1.w;
            float4 b0 = *(float4*)&Bs[k][tx * 8];
            float4 b1 = *(float4*)&Bs[k][tx * 8 + 4];
            b[0]=b0.x; b[1]=b0.y; b[2]=b0.z; b[3]=b0.w;
            b[4]=b1.x; b[5]=b1.y; b[6]=b1.z; b[7]=b1.w;
#pragma unroll
            for (int i = 0; i < 8; i++)
#pragma unroll
                for (int j = 0; j < 8; j++) acc[i][j] = fmaf(a[i], b[j], acc[i][j]);
        }
        __syncthreads();
    }

#pragma unroll
    for (int i = 0; i < 8; i++) {
        const int mrow = mBase + ty * 8 + i;
        float* crow = C + (size_t)mrow * DIM_ + nBase + tx * 8;
        const float* rrow = (MODE == 1) ? (res + (size_t)mrow * DIM_ + nBase + tx * 8) : nullptr;
#pragma unroll
        for (int j = 0; j < 8; j += 4) {
            float4 bv = *(const float4*)&bias[nBase + tx * 8 + j];
            float4 cv;
            if (MODE == 0) {
                cv.x = acc[i][j + 0] + bv.x;
                cv.y = acc[i][j + 1] + bv.y;
                cv.z = acc[i][j + 2] + bv.z;
                cv.w = acc[i][j + 3] + bv.w;
            } else {
                float4 rv = *(const float4*)&rrow[j];
                cv.x = rv.x + fmaxf(acc[i][j + 0] + bv.x, 0.f);
                cv.y = rv.y + fmaxf(acc[i][j + 1] + bv.y, 0.f);
                cv.z = rv.z + fmaxf(acc[i][j + 2] + bv.z, 0.f);
                cv.w = rv.w + fmaxf(acc[i][j + 3] + bv.w, 0.f);
            }
            *(float4*)&crow[j] = cv;
        }
    }
}

// ---------------- flash attention + in-head residual ----------------
// grid: (B*H, NQ/128). 256 threads = 16x16 (tx over 64 keys/vcols by 4, ty over 128 q-rows by 8).
// smem: Qs[128][64] | Kst[64][64] (kk-major) | Vs[64][64] | Ps[128][64]  = 96 KB
#define ATT_SMEM_FLOATS (128 * 64 + 64 * 64 + 64 * 64 + 128 * 64)

__global__ __launch_bounds__(256) void attn_kernel(const float* __restrict__ Qp,
                                                   const float* __restrict__ Kp,
                                                   const float* __restrict__ Vp,
                                                   float* __restrict__ O) {
    extern __shared__ float sm[];
    float* Qs  = sm;                      // [128][64]
    float* Kst = Qs + 128 * 64;           // [64(kk)][64(key)]
    float* Vs  = Kst + 64 * 64;           // [64(key)][64(v)]
    float* Ps  = Vs + 64 * 64;            // [128][64]

    const int tid = threadIdx.x;
    const int tx = tid & 15;
    const int ty = tid >> 4;
    const int bh = blockIdx.x;
    const int b = bh >> 3, h = bh & 7;
    const int q0 = blockIdx.y * 128;

    const float* Qbase = Qp + ((size_t)b * NQ_ + q0) * DIM_ + h * HD_;
    const float* Kbase = Kp + ((size_t)b * NK_) * DIM_ + h * HD_;
    const float* Vbase = Vp + ((size_t)b * NK_) * DIM_ + h * HD_;
    float* Obase = O + ((size_t)b * NQ_ + q0) * DIM_ + h * HD_;

    // load + pre-scale Q tile
#pragma unroll
    for (int i = 0; i < 8; i++) {
        int f = tid + i * 256;            // 0..2047
        int q = f >> 4;
        int c4 = (f & 15) << 2;
        float4 v = *(const float4*)&Qbase[(size_t)q * DIM_ + c4];
        v.x *= SCALE_; v.y *= SCALE_; v.z *= SCALE_; v.w *= SCALE_;
        *(float4*)&Qs[q * 64 + c4] = v;
    }

    float m[8], l[8], o[8][4];
#pragma unroll
    for (int i = 0; i < 8; i++) {
        m[i] = -1e30f; l[i] = 0.f;
#pragma unroll
        for (int c = 0; c < 4; c++) o[i][c] = 0.f;
    }

    for (int k0 = 0; k0 < NK_; k0 += 64) {
        __syncthreads();   // previous PV readers done (also orders Qs store on iter 0)
#pragma unroll
        for (int i = 0; i < 4; i++) {
            int f = tid + i * 256;        // 0..1023
            int key = f >> 4;
            int c4 = (f & 15) << 2;
            float4 kv = *(const float4*)&Kbase[(size_t)(k0 + key) * DIM_ + c4];
            Kst[(c4 + 0) * 64 + key] = kv.x;
            Kst[(c4 + 1) * 64 + key] = kv.y;
            Kst[(c4 + 2) * 64 + key] = kv.z;
            Kst[(c4 + 3) * 64 + key] = kv.w;
            *(float4*)&Vs[key * 64 + c4] =
                *(const float4*)&Vbase[(size_t)(k0 + key) * DIM_ + c4];
        }
        __syncthreads();

        // S = (Q*scale) @ K^T  -> s[8][4]
        float s[8][4];
#pragma unroll
        for (int i = 0; i < 8; i++)
#pragma unroll
            for (int c = 0; c < 4; c++) s[i][c] = 0.f;

#pragma unroll 8
        for (int kk = 0; kk < 64; kk++) {
            float4 kf = *(float4*)&Kst[kk * 64 + tx * 4];
#pragma unroll
            for (int i = 0; i < 8; i++) {
                float qv = Qs[(ty * 8 + i) * 64 + kk];
                s[i][0] = fmaf(qv, kf.x, s[i][0]);
                s[i][1] = fmaf(qv, kf.y, s[i][1]);
                s[i][2] = fmaf(qv, kf.z, s[i][2]);
                s[i][3] = fmaf(qv, kf.w, s[i][3]);
            }
        }

        // online softmax update (row reduce over 16-lane tx groups)
#pragma unroll
        for (int i = 0; i < 8; i++) {
            float mx = fmaxf(fmaxf(s[i][0], s[i][1]), fmaxf(s[i][2], s[i][3]));
#pragma unroll
            for (int d = 8; d > 0; d >>= 1)
                mx = fmaxf(mx, __shfl_xor_sync(0xffffffffu, mx, d));
            float mn = fmaxf(m[i], mx);
            float corr = __expf(m[i] - mn);
            float p0 = __expf(s[i][0] - mn);
            float p1 = __expf(s[i][1] - mn);
            float p2 = __expf(s[i][2] - mn);
            float p3 = __expf(s[i][3] - mn);
            float rs = (p0 + p1) + (p2 + p3);
#pragma unroll
            for (int d = 8; d > 0; d >>= 1)
                rs += __shfl_xor_sync(0xffffffffu, rs, d);
            l[i] = l[i] * corr + rs;
            m[i] = mn;
            o[i][0] *= corr; o[i][1] *= corr; o[i][2] *= corr; o[i][3] *= corr;
            float4 pv = make_float4(p0, p1, p2, p3);
            *(float4*)&Ps[(ty * 8 + i) * 64 + tx * 4] = pv;
        }
        __syncthreads();

        // O += P @ V
#pragma unroll 8
        for (int key = 0; key < 64; key++) {
            float4 vf = *(float4*)&Vs[key * 64 + tx * 4];
#pragma unroll
            for (int i = 0; i < 8; i++) {
                float p = Ps[(ty * 8 + i) * 64 + key];
                o[i][0] = fmaf(p, vf.x, o[i][0]);
                o[i][1] = fmaf(p, vf.y, o[i][1]);
                o[i][2] = fmaf(p, vf.z, o[i][2]);
                o[i][3] = fmaf(p, vf.w, o[i][3]);
            }
        }
    }

    // epilogue: O = Qp + attn/l
#pragma unroll
    for (int i = 0; i < 8; i++) {
        float inv = 1.f / l[i];
        int q = ty * 8 + i;
        size_t off = (size_t)q * DIM_ + tx * 4;
        float4 qp = *(const float4*)&Qbase[off];
        float4 ov;
        ov.x = qp.x + o[i][0] * inv;
        ov.y = qp.y + o[i][1] * inv;
        ov.z = qp.z + o[i][2] * inv;
        ov.w = qp.w + o[i][3] * inv;
        *(float4*)&Obase[off] = ov;
    }
}

// ---------------- LayerNorm over last dim 512 (warp per row) ----------------
__global__ __launch_bounds__(256) void layernorm512(const float* __restrict__ X,
                                                    const float* __restrict__ gam,
                                                    const float* __restrict__ bet,
                                                    float* __restrict__ Y) {
    const int warp = threadIdx.x >> 5;
    const int lane = threadIdx.x & 31;
    const int row = blockIdx.x * 8 + warp;
    if (row >= MROWS) return;
    const float* x = X + (size_t)row * DIM_;
    float v[16];
    float s = 0.f, sq = 0.f;
#pragma unroll
    for (int j = 0; j < 16; j++) {
        v[j] = x[lane + j * 32];
        s += v[j];
        sq = fmaf(v[j], v[j], sq);
    }
#pragma unroll
    for (int d = 16; d > 0; d >>= 1) {
        s  += __shfl_xor_sync(0xffffffffu, s, d);
        sq += __shfl_xor_sync(0xffffffffu, sq, d);
    }
    float mean = s * (1.f / DIM_);
    float var = sq * (1.f / DIM_) - mean * mean;
    float rs = rsqrtf(var + 1e-5f);
    float* y = Y + (size_t)row * DIM_;
#pragma unroll
    for (int j = 0; j < 16; j++) {
        int col = lane + j * 32;
        y[col] = (v[j] - mean) * rs * gam[col] + bet[col];
    }
}

// ---------------- launch ----------------
extern "C" void kernel_launch(void* const* d_in, const int* in_sizes, int n_in,
                              void* d_out, int out_size) {
    const float* Q   = (const float*)d_in[0];
    const float* K   = (const float*)d_in[1];
    const float* Wq  = (const float*)d_in[2];
    const float* bq  = (const float*)d_in[3];
    const float* Wk  = (const float*)d_in[4];
    const float* bk  = (const float*)d_in[5];
    const float* Wv  = (const float*)d_in[6];
    const float* bv  = (const float*)d_in[7];
    const float* Wo  = (const float*)d_in[8];
    const float* bo  = (const float*)d_in[9];
    const float* g0  = (const float*)d_in[10];
    const float* be0 = (const float*)d_in[11];
    const float* g1  = (const float*)d_in[12];
    const float* be1 = (const float*)d_in[13];
    float* out = (float*)d_out;

    float *Qp, *Kp, *Vp, *O, *O2;
    cudaGetSymbolAddress((void**)&Qp, g_Qp);
    cudaGetSymbolAddress((void**)&Kp, g_Kp);
    cudaGetSymbolAddress((void**)&Vp, g_Vp);
    cudaGetSymbolAddress((void**)&O,  g_O);
    cudaGetSymbolAddress((void**)&O2, g_O2);

    const int attSmem = ATT_SMEM_FLOATS * sizeof(float);   // 96 KB
    cudaFuncSetAttribute(attn_kernel, cudaFuncAttributeMaxDynamicSharedMemorySize, attSmem);

    dim3 gGrid(DIM_ / 128, MROWS / 128);   // (4, 64)

    gemm512<0><<<gGrid, 256>>>(Q, Wq, bq, nullptr, Qp);
    gemm512<0><<<gGrid, 256>>>(K, Wk, bk, nullptr, Kp);
    gemm512<0><<<gGrid, 256>>>(K, Wv, bv, nullptr, Vp);

    attn_kernel<<<dim3(B_ * H_, NQ_ / 128), 256, attSmem>>>(Qp, Kp, Vp, O);

    layernorm512<<<MROWS / 8, 256>>>(O, g0, be0, O);

    gemm512<1><<<gGrid, 256>>>(O, Wo, bo, O, O2);

    layernorm512<<<MROWS / 8, 256>>>(O2, g1, be1, out);
}

// round 3
// speedup vs baseline: 1.6264x; 1.6264x over previous
#include <cuda_runtime.h>
#include <cuda_bf16.h>
#include <math.h>
#include <stdint.h>

// Problem constants
#define B_     8
#define NQ_    1024
#define NK_    1024
#define DIM_   512
#define H_     8
#define HD_    64
#define MROWS  (B_ * NQ_)     // 8192
#define SCALE_ 0.04419417382415922f   // 1/sqrt(512)

// ---------------- scratch ----------------
__device__ float g_Qp[MROWS * DIM_];
__device__ float g_Kp[MROWS * DIM_];
__device__ float g_Vp[MROWS * DIM_];
__device__ float g_O [MROWS * DIM_];
__device__ float g_O2[MROWS * DIM_];

// ---------------- helpers ----------------
__device__ __forceinline__ uint32_t smem_u32(const void* p) {
    uint32_t a;
    asm("{ .reg .u64 t; cvta.to.shared.u64 t, %1; cvt.u32.u64 %0, t; }" : "=r"(a) : "l"(p));
    return a;
}
#define SW128(b) ((b) ^ (((b) >> 3) & 0x70))

__device__ __forceinline__ void ldsm4(uint32_t& r0, uint32_t& r1, uint32_t& r2, uint32_t& r3,
                                      uint32_t addr) {
    asm volatile("ldmatrix.sync.aligned.m8n8.x4.shared.b16 {%0,%1,%2,%3}, [%4];"
                 : "=r"(r0), "=r"(r1), "=r"(r2), "=r"(r3) : "r"(addr));
}

__device__ __forceinline__ void mma_bf16(float* c, const uint32_t* a, uint32_t b0, uint32_t b1) {
    asm volatile(
        "mma.sync.aligned.m16n8k16.row.col.f32.bf16.bf16.f32 "
        "{%0,%1,%2,%3}, {%4,%5,%6,%7}, {%8,%9}, {%0,%1,%2,%3};"
        : "+f"(c[0]), "+f"(c[1]), "+f"(c[2]), "+f"(c[3])
        : "r"(a[0]), "r"(a[1]), "r"(a[2]), "r"(a[3]), "r"(b0), "r"(b1));
}

__device__ __forceinline__ uint32_t pack_bf2(__nv_bfloat16 a, __nv_bfloat16 b) {
    uint16_t ua = *reinterpret_cast<uint16_t*>(&a);
    uint16_t ub = *reinterpret_cast<uint16_t*>(&b);
    return (uint32_t)ua | ((uint32_t)ub << 16);
}
__device__ __forceinline__ void bsplit(float x, __nv_bfloat16& h, __nv_bfloat16& l) {
    h = __float2bfloat16(x);
    l = __float2bfloat16(x - __bfloat162float(h));
}

// ======================= bf16x3 mma.sync GEMM =======================
// C[M,512] = A[M,512] @ W[512,512] (+bias; MODE1: res + relu epilogue)
// CTA 128x128, 256 thr, 8 warps (2m x 4n), warp tile 64x32, K-chunk 64.
// smem: Ah[128][64]bf16 @0, Al @16384, Bh[128n][64k] @32768, Bl @49152  = 64KB
#define GSMEM_BYTES 65536

template <int MODE>
__global__ __launch_bounds__(256) void gemm_mma(const float* __restrict__ A,
                                                const float* __restrict__ W,
                                                const float* __restrict__ bias,
                                                const float* __restrict__ res,
                                                float* __restrict__ C) {
    extern __shared__ __align__(1024) char sm[];
    const uint32_t sb = smem_u32(sm);
    const int tid = threadIdx.x, lane = tid & 31, wid = tid >> 5;
    const int wm = wid & 1, wn = wid >> 1;               // 2 x 4 warp grid
    const int mBase = blockIdx.y * 128, nBase = blockIdx.x * 128;

    const uint32_t AH = 0, AL = 16384, BH = 32768, BL = 49152;

    float acc[4][4][4];
#pragma unroll
    for (int i = 0; i < 4; i++)
#pragma unroll
        for (int j = 0; j < 4; j++)
#pragma unroll
            for (int c = 0; c < 4; c++) acc[i][j][c] = 0.f;

    // precomputed ldmatrix address components
    const uint32_t a_row = (lane & 15);
    const uint32_t a_colb = (lane >> 4) * 16;           // 0 or 16
    const uint32_t b_rowsub = ((lane >> 4) * 8) + (lane & 7);   // frag sel + row
    const uint32_t b_colb = ((lane >> 3) & 1) * 16;

    for (int kc = 0; kc < 8; kc++) {
        __syncthreads();
        // ---- load + split A chunk [128][64] ----
        {
            const float* Ab = A + (size_t)mBase * DIM_ + kc * 64;
#pragma unroll
            for (int i = 0; i < 8; i++) {
                int f = tid + i * 256;
                int r = f >> 4;
                int c4 = (f & 15) << 2;
                float4 v = *(const float4*)(Ab + (size_t)r * DIM_ + c4);
                __nv_bfloat16 hx, lx, hy, ly, hz, lz, hw, lw;
                bsplit(v.x, hx, lx); bsplit(v.y, hy, ly);
                bsplit(v.z, hz, lz); bsplit(v.w, hw, lw);
                uint32_t so = SW128((uint32_t)(r * 128 + c4 * 2));
                *(uint2*)(sm + AH + so) = make_uint2(pack_bf2(hx, hy), pack_bf2(hz, hw));
                *(uint2*)(sm + AL + so) = make_uint2(pack_bf2(lx, ly), pack_bf2(lz, lw));
            }
        }
        // ---- load + split + transpose W chunk -> B[n][k] ----
        {
            const float* Wb = W + (size_t)(kc * 64) * DIM_ + nBase;
#pragma unroll
            for (int i = 0; i < 4; i++) {
                int f = tid + i * 256;
                int k2 = f & 31;
                int n4 = ((f >> 5) & 31) << 2;
                const float* w0 = Wb + (size_t)(2 * k2) * DIM_ + n4;
                float4 r0 = *(const float4*)w0;
                float4 r1 = *(const float4*)(w0 + DIM_);
                float p0[4] = {r0.x, r0.y, r0.z, r0.w};
                float p1[4] = {r1.x, r1.y, r1.z, r1.w};
#pragma unroll
                for (int j = 0; j < 4; j++) {
                    __nv_bfloat16 h0, l0, h1, l1;
                    bsplit(p0[j], h0, l0);
                    bsplit(p1[j], h1, l1);
                    uint32_t so = SW128((uint32_t)((n4 + j) * 128 + k2 * 4));
                    *(uint32_t*)(sm + BH + so) = pack_bf2(h0, h1);
                    *(uint32_t*)(sm + BL + so) = pack_bf2(l0, l1);
                }
            }
        }
        __syncthreads();

        // ---- compute: 4 k16 steps ----
#pragma unroll
        for (int ks = 0; ks < 4; ks++) {
            uint32_t ah[4][4], al[4][4];
#pragma unroll
            for (int mf = 0; mf < 4; mf++) {
                uint32_t off = (uint32_t)((wm * 64 + mf * 16 + a_row) * 128 + ks * 32 + a_colb);
                ldsm4(ah[mf][0], ah[mf][1], ah[mf][2], ah[mf][3], sb + AH + SW128(off));
                ldsm4(al[mf][0], al[mf][1], al[mf][2], al[mf][3], sb + AL + SW128(off));
            }
#pragma unroll
            for (int j = 0; j < 4; j += 2) {
                uint32_t off = (uint32_t)((wn * 32 + j * 8 + b_rowsub) * 128 + ks * 32 + b_colb);
                uint32_t bh0, bh1, bh2, bh3, bl0, bl1, bl2, bl3;
                ldsm4(bh0, bh1, bh2, bh3, sb + BH + SW128(off));
                ldsm4(bl0, bl1, bl2, bl3, sb + BL + SW128(off));
#pragma unroll
                for (int mf = 0; mf < 4; mf++) {
                    mma_bf16(acc[mf][j],     ah[mf], bh0, bh1);
                    mma_bf16(acc[mf][j],     ah[mf], bl0, bl1);
                    mma_bf16(acc[mf][j],     al[mf], bh0, bh1);
                    mma_bf16(acc[mf][j + 1], ah[mf], bh2, bh3);
                    mma_bf16(acc[mf][j + 1], ah[mf], bl2, bl3);
                    mma_bf16(acc[mf][j + 1], al[mf], bh2, bh3);
                }
            }
        }
    }

    // ---- epilogue ----
#pragma unroll
    for (int mf = 0; mf < 4; mf++) {
        int row0 = mBase + wm * 64 + mf * 16 + (lane >> 2);
#pragma unroll
        for (int nf = 0; nf < 4; nf++) {
            int col = nBase + wn * 32 + nf * 8 + 2 * (lane & 3);
            float b0 = bias[col], b1 = bias[col + 1];
            float x0 = acc[mf][nf][0] + b0, x1 = acc[mf][nf][1] + b1;
            float x2 = acc[mf][nf][2] + b0, x3 = acc[mf][nf][3] + b1;
            float* p0 = C + (size_t)row0 * DIM_ + col;
            float* p1 = C + (size_t)(row0 + 8) * DIM_ + col;
            if (MODE == 0) {
                *(float2*)p0 = make_float2(x0, x1);
                *(float2*)p1 = make_float2(x2, x3);
            } else {
                const float* r0p = res + (size_t)row0 * DIM_ + col;
                const float* r1p = res + (size_t)(row0 + 8) * DIM_ + col;
                float2 rv0 = *(const float2*)r0p;
                float2 rv1 = *(const float2*)r1p;
                *(float2*)p0 = make_float2(rv0.x + fmaxf(x0, 0.f), rv0.y + fmaxf(x1, 0.f));
                *(float2*)p1 = make_float2(rv1.x + fmaxf(x2, 0.f), rv1.y + fmaxf(x3, 0.f));
            }
        }
    }
}

// ======================= mma.sync flash attention =======================
// grid (B*H, NQ/128). 256 thr, 8 warps; warp w owns q rows [16w,16w+16).
// Keys chunked by 64. S = Q K^T (bf16x3), online softmax on fragments,
// P fed register-to-register into PV mma (bf16x3). O = Qp + attn.
// smem 32KB: Q staging (hi@0 16K, lo@16384) then reused as
// Kh@0(8K) Kl@8192 Vh@16384 Vl@24576.
__global__ __launch_bounds__(256) void attn_mma(const float* __restrict__ Qp,
                                                const float* __restrict__ Kp,
                                                const float* __restrict__ Vp,
                                                float* __restrict__ O) {
    __shared__ __align__(1024) char sm[32768];
    const uint32_t sb = smem_u32(sm);
    const int tid = threadIdx.x, lane = tid & 31, wid = tid >> 5;
    const int bh = blockIdx.x;
    const int b = bh >> 3, h = bh & 7;
    const int q0 = blockIdx.y * 128;

    const float* Qbase = Qp + ((size_t)b * NQ_ + q0) * DIM_ + h * HD_;
    const float* Kbase = Kp + ((size_t)b * NK_) * DIM_ + h * HD_;
    const float* Vbase = Vp + ((size_t)b * NK_) * DIM_ + h * HD_;
    float* Obase = O + ((size_t)b * NQ_ + q0) * DIM_ + h * HD_;

    // ---- stage Q (scaled) as bf16 hi/lo ----
#pragma unroll
    for (int i = 0; i < 8; i++) {
        int f = tid + i * 256;
        int r = f >> 4;
        int c4 = (f & 15) << 2;
        float4 v = *(const float4*)&Qbase[(size_t)r * DIM_ + c4];
        v.x *= SCALE_; v.y *= SCALE_; v.z *= SCALE_; v.w *= SCALE_;
        __nv_bfloat16 hx, lx, hy, ly, hz, lz, hw, lw;
        bsplit(v.x, hx, lx); bsplit(v.y, hy, ly);
        bsplit(v.z, hz, lz); bsplit(v.w, hw, lw);
        uint32_t so = SW128((uint32_t)(r * 128 + c4 * 2));
        *(uint2*)(sm + so)         = make_uint2(pack_bf2(hx, hy), pack_bf2(hz, hw));
        *(uint2*)(sm + 16384 + so) = make_uint2(pack_bf2(lx, ly), pack_bf2(lz, lw));
    }
    __syncthreads();

    // ---- extract Q fragments to registers ----
    const uint32_t a_row = (lane & 15);
    const uint32_t a_colb = (lane >> 4) * 16;
    const uint32_t b_rowsub = ((lane >> 4) * 8) + (lane & 7);
    const uint32_t b_colb = ((lane >> 3) & 1) * 16;

    uint32_t qh[4][4], ql[4][4];
#pragma unroll
    for (int ks = 0; ks < 4; ks++) {
        uint32_t off = (uint32_t)((wid * 16 + a_row) * 128 + ks * 32 + a_colb);
        ldsm4(qh[ks][0], qh[ks][1], qh[ks][2], qh[ks][3], sb + SW128(off));
        ldsm4(ql[ks][0], ql[ks][1], ql[ks][2], ql[ks][3], sb + 16384 + SW128(off));
    }
    __syncthreads();   // Q staging free -> reuse for K/V

    const uint32_t KH = 0, KL = 8192, VH = 16384, VL = 24576;

    float o[8][4];
#pragma unroll
    for (int nf = 0; nf < 8; nf++)
#pragma unroll
        for (int c = 0; c < 4; c++) o[nf][c] = 0.f;
    float m0 = -1e30f, m1 = -1e30f, l0 = 0.f, l1 = 0.f;

    for (int kc = 0; kc < 16; kc++) {
        __syncthreads();
        // ---- load K chunk [64 key][64 d] hi/lo ----
#pragma unroll
        for (int i = 0; i < 4; i++) {
            int f = tid + i * 256;
            int r = f >> 4;                 // key 0..63
            int c4 = (f & 15) << 2;
            float4 v = *(const float4*)&Kbase[(size_t)(kc * 64 + r) * DIM_ + c4];
            __nv_bfloat16 hx, lx, hy, ly, hz, lz, hw, lw;
            bsplit(v.x, hx, lx); bsplit(v.y, hy, ly);
            bsplit(v.z, hz, lz); bsplit(v.w, hw, lw);
            uint32_t so = SW128((uint32_t)(r * 128 + c4 * 2));
            *(uint2*)(sm + KH + so) = make_uint2(pack_bf2(hx, hy), pack_bf2(hz, hw));
            *(uint2*)(sm + KL + so) = make_uint2(pack_bf2(lx, ly), pack_bf2(lz, lw));
        }
        // ---- load V chunk transposed -> Vst[d][key] hi/lo ----
#pragma unroll
        for (int i = 0; i < 2; i++) {
            int f = tid + i * 256;
            int k2 = f & 31;                 // key pair
            int n4 = ((f >> 5) & 15) << 2;   // d col
            const float* v0 = &Vbase[(size_t)(kc * 64 + 2 * k2) * DIM_ + n4];
            float4 r0 = *(const float4*)v0;
            float4 r1 = *(const float4*)(v0 + DIM_);
            float p0[4] = {r0.x, r0.y, r0.z, r0.w};
            float p1[4] = {r1.x, r1.y, r1.z, r1.w};
#pragma unroll
            for (int j = 0; j < 4; j++) {
                __nv_bfloat16 h0, lo0, h1, lo1;
                bsplit(p0[j], h0, lo0);
                bsplit(p1[j], h1, lo1);
                uint32_t so = SW128((uint32_t)((n4 + j) * 128 + k2 * 4));
                *(uint32_t*)(sm + VH + so) = pack_bf2(h0, h1);
                *(uint32_t*)(sm + VL + so) = pack_bf2(lo0, lo1);
            }
        }
        __syncthreads();

        // ---- S = Q K^T ----
        float s[8][4];
#pragma unroll
        for (int nf = 0; nf < 8; nf++)
#pragma unroll
            for (int c = 0; c < 4; c++) s[nf][c] = 0.f;

#pragma unroll
        for (int ks = 0; ks < 4; ks++) {
#pragma unroll
            for (int j = 0; j < 8; j += 2) {
                uint32_t off = (uint32_t)((j * 8 + b_rowsub) * 128 + ks * 32 + b_colb);
                uint32_t bh0, bh1, bh2, bh3, bl0, bl1, bl2, bl3;
                ldsm4(bh0, bh1, bh2, bh3, sb + KH + SW128(off));
                ldsm4(bl0, bl1, bl2, bl3, sb + KL + SW128(off));
                mma_bf16(s[j],     qh[ks], bh0, bh1);
                mma_bf16(s[j],     qh[ks], bl0, bl1);
                mma_bf16(s[j],     ql[ks], bh0, bh1);
                mma_bf16(s[j + 1], qh[ks], bh2, bh3);
                mma_bf16(s[j + 1], qh[ks], bl2, bl3);
                mma_bf16(s[j + 1], ql[ks], bh2, bh3);
            }
        }

        // ---- online softmax (rows lane>>2 and lane>>2+8) ----
        float mx0 = -1e30f, mx1 = -1e30f;
#pragma unroll
        for (int nf = 0; nf < 8; nf++) {
            mx0 = fmaxf(mx0, fmaxf(s[nf][0], s[nf][1]));
            mx1 = fmaxf(mx1, fmaxf(s[nf][2], s[nf][3]));
        }
        mx0 = fmaxf(mx0, __shfl_xor_sync(0xffffffffu, mx0, 1));
        mx0 = fmaxf(mx0, __shfl_xor_sync(0xffffffffu, mx0, 2));
        mx1 = fmaxf(mx1, __shfl_xor_sync(0xffffffffu, mx1, 1));
        mx1 = fmaxf(mx1, __shfl_xor_sync(0xffffffffu, mx1, 2));
        float mn0 = fmaxf(m0, mx0), mn1 = fmaxf(m1, mx1);
        float corr0 = __expf(m0 - mn0), corr1 = __expf(m1 - mn1);
        float sum0 = 0.f, sum1 = 0.f;
#pragma unroll
        for (int nf = 0; nf < 8; nf++) {
            s[nf][0] = __expf(s[nf][0] - mn0);
            s[nf][1] = __expf(s[nf][1] - mn0);
            s[nf][2] = __expf(s[nf][2] - mn1);
            s[nf][3] = __expf(s[nf][3] - mn1);
            sum0 += s[nf][0] + s[nf][1];
            sum1 += s[nf][2] + s[nf][3];
        }
        sum0 += __shfl_xor_sync(0xffffffffu, sum0, 1);
        sum0 += __shfl_xor_sync(0xffffffffu, sum0, 2);
        sum1 += __shfl_xor_sync(0xffffffffu, sum1, 1);
        sum1 += __shfl_xor_sync(0xffffffffu, sum1, 2);
        l0 = l0 * corr0 + sum0;
        l1 = l1 * corr1 + sum1;
        m0 = mn0; m1 = mn1;
#pragma unroll
        for (int nf = 0; nf < 8; nf++) {
            o[nf][0] *= corr0; o[nf][1] *= corr0;
            o[nf][2] *= corr1; o[nf][3] *= corr1;
        }

        // ---- convert P -> A fragments (hi/lo), register-only ----
        uint32_t pa_h[4][4], pa_l[4][4];
#pragma unroll
        for (int ks = 0; ks < 4; ks++) {
#pragma unroll
            for (int half = 0; half < 2; half++) {        // frag 2ks, 2ks+1
                int nf = 2 * ks + half;
                __nv_bfloat16 h0, lo0, h1, lo1, h2, lo2, h3, lo3;
                bsplit(s[nf][0], h0, lo0);
                bsplit(s[nf][1], h1, lo1);
                bsplit(s[nf][2], h2, lo2);
                bsplit(s[nf][3], h3, lo3);
                pa_h[ks][2 * half + 0] = pack_bf2(h0, h1);
                pa_h[ks][2 * half + 1] = pack_bf2(h2, h3);
                pa_l[ks][2 * half + 0] = pack_bf2(lo0, lo1);
                pa_l[ks][2 * half + 1] = pack_bf2(lo2, lo3);
            }
        }
        // NOTE: pa regs ordering: a0 = (frag 2ks rows r), a1 = (frag 2ks rows r+8),
        // a2 = (frag 2ks+1 rows r), a3 = (frag 2ks+1 rows r+8).
        // half=0 -> indices 0,1 ; half=1 -> 2,3 : matches a0..a3.

        // ---- O += P V ----
#pragma unroll
        for (int ks = 0; ks < 4; ks++) {
#pragma unroll
            for (int j = 0; j < 8; j += 2) {
                uint32_t off = (uint32_t)((j * 8 + b_rowsub) * 128 + ks * 32 + b_colb);
                uint32_t bh0, bh1, bh2, bh3, bl0, bl1, bl2, bl3;
                ldsm4(bh0, bh1, bh2, bh3, sb + VH + SW128(off));
                ldsm4(bl0, bl1, bl2, bl3, sb + VL + SW128(off));
                mma_bf16(o[j],     pa_h[ks], bh0, bh1);
                mma_bf16(o[j],     pa_h[ks], bl0, bl1);
                mma_bf16(o[j],     pa_l[ks], bh0, bh1);
                mma_bf16(o[j + 1], pa_h[ks], bh2, bh3);
                mma_bf16(o[j + 1], pa_h[ks], bl2, bl3);
                mma_bf16(o[j + 1], pa_l[ks], bh2, bh3);
            }
        }
    }

    // ---- epilogue: O = Qp + attn / l ----
    float inv0 = 1.f / l0, inv1 = 1.f / l1;
    int r0 = wid * 16 + (lane >> 2);
    int r1 = r0 + 8;
#pragma unroll
    for (int nf = 0; nf < 8; nf++) {
        int col = nf * 8 + 2 * (lane & 3);
        const float* q0p = &Qbase[(size_t)r0 * DIM_ + col];
        const float* q1p = &Qbase[(size_t)r1 * DIM_ + col];
        float2 qv0 = *(const float2*)q0p;
        float2 qv1 = *(const float2*)q1p;
        *(float2*)&Obase[(size_t)r0 * DIM_ + col] =
            make_float2(qv0.x + o[nf][0] * inv0, qv0.y + o[nf][1] * inv0);
        *(float2*)&Obase[(size_t)r1 * DIM_ + col] =
            make_float2(qv1.x + o[nf][2] * inv1, qv1.y + o[nf][3] * inv1);
    }
}

// ---------------- LayerNorm over last dim 512 (warp per row) ----------------
__global__ __launch_bounds__(256) void layernorm512(const float* __restrict__ X,
                                                    const float* __restrict__ gam,
                                                    const float* __restrict__ bet,
                                                    float* __restrict__ Y) {
    const int warp = threadIdx.x >> 5;
    const int lane = threadIdx.x & 31;
    const int row = blockIdx.x * 8 + warp;
    if (row >= MROWS) return;
    const float* x = X + (size_t)row * DIM_;
    float v[16];
    float s = 0.f, sq = 0.f;
#pragma unroll
    for (int j = 0; j < 16; j++) {
        v[j] = x[lane + j * 32];
        s += v[j];
        sq = fmaf(v[j], v[j], sq);
    }
#pragma unroll
    for (int d = 16; d > 0; d >>= 1) {
        s  += __shfl_xor_sync(0xffffffffu, s, d);
        sq += __shfl_xor_sync(0xffffffffu, sq, d);
    }
    float mean = s * (1.f / DIM_);
    float var = sq * (1.f / DIM_) - mean * mean;
    float rs = rsqrtf(var + 1e-5f);
    float* y = Y + (size_t)row * DIM_;
#pragma unroll
    for (int j = 0; j < 16; j++) {
        int col = lane + j * 32;
        y[col] = (v[j] - mean) * rs * gam[col] + bet[col];
    }
}

// ---------------- launch ----------------
extern "C" void kernel_launch(void* const* d_in, const int* in_sizes, int n_in,
                              void* d_out, int out_size) {
    const float* Q   = (const float*)d_in[0];
    const float* K   = (const float*)d_in[1];
    const float* Wq  = (const float*)d_in[2];
    const float* bq  = (const float*)d_in[3];
    const float* Wk  = (const float*)d_in[4];
    const float* bk  = (const float*)d_in[5];
    const float* Wv  = (const float*)d_in[6];
    const float* bv  = (const float*)d_in[7];
    const float* Wo  = (const float*)d_in[8];
    const float* bo  = (const float*)d_in[9];
    const float* g0  = (const float*)d_in[10];
    const float* be0 = (const float*)d_in[11];
    const float* g1  = (const float*)d_in[12];
    const float* be1 = (const float*)d_in[13];
    float* out = (float*)d_out;

    float *Qp, *Kp, *Vp, *O, *O2;
    cudaGetSymbolAddress((void**)&Qp, g_Qp);
    cudaGetSymbolAddress((void**)&Kp, g_Kp);
    cudaGetSymbolAddress((void**)&Vp, g_Vp);
    cudaGetSymbolAddress((void**)&O,  g_O);
    cudaGetSymbolAddress((void**)&O2, g_O2);

    cudaFuncSetAttribute(gemm_mma<0>, cudaFuncAttributeMaxDynamicSharedMemorySize, GSMEM_BYTES);
    cudaFuncSetAttribute(gemm_mma<1>, cudaFuncAttributeMaxDynamicSharedMemorySize, GSMEM_BYTES);

    dim3 gGrid(DIM_ / 128, MROWS / 128);   // (4, 64)

    gemm_mma<0><<<gGrid, 256, GSMEM_BYTES>>>(Q, Wq, bq, nullptr, Qp);
    gemm_mma<0><<<gGrid, 256, GSMEM_BYTES>>>(K, Wk, bk, nullptr, Kp);
    gemm_mma<0><<<gGrid, 256, GSMEM_BYTES>>>(K, Wv, bv, nullptr, Vp);

    attn_mma<<<dim3(B_ * H_, NQ_ / 128), 256>>>(Qp, Kp, Vp, O);

    layernorm512<<<MROWS / 8, 256>>>(O, g0, be0, O);

    gemm_mma<1><<<gGrid, 256, GSMEM_BYTES>>>(O, Wo, bo, O, O2);

    layernorm512<<<MROWS / 8, 256>>>(O2, g1, be1, out);
}

// round 4
// speedup vs baseline: 1.6519x; 1.0157x over previous
#include <cuda_runtime.h>
#include <cuda_bf16.h>
#include <math.h>
#include <stdint.h>

// Problem constants
#define B_     8
#define NQ_    1024
#define NK_    1024
#define DIM_   512
#define H_     8
#define HD_    64
#define MROWS  (B_ * NQ_)     // 8192
#define SCALE_ 0.04419417382415922f   // 1/sqrt(512)

// ---------------- scratch ----------------
__device__ float g_Qp[MROWS * DIM_];
__device__ float g_Kp[MROWS * DIM_];
__device__ float g_Vp[MROWS * DIM_];
__device__ float g_O [MROWS * DIM_];
__device__ float g_O2[MROWS * DIM_];

// ---------------- helpers ----------------
__device__ __forceinline__ uint32_t smem_u32(const void* p) {
    uint32_t a;
    asm("{ .reg .u64 t; cvta.to.shared.u64 t, %1; cvt.u32.u64 %0, t; }" : "=r"(a) : "l"(p));
    return a;
}
#define SW128(b) ((b) ^ (((b) >> 3) & 0x70))

__device__ __forceinline__ void ldsm4(uint32_t& r0, uint32_t& r1, uint32_t& r2, uint32_t& r3,
                                      uint32_t addr) {
    asm volatile("ldmatrix.sync.aligned.m8n8.x4.shared.b16 {%0,%1,%2,%3}, [%4];"
                 : "=r"(r0), "=r"(r1), "=r"(r2), "=r"(r3) : "r"(addr));
}

__device__ __forceinline__ void mma_bf16(float* c, const uint32_t* a, uint32_t b0, uint32_t b1) {
    asm volatile(
        "mma.sync.aligned.m16n8k16.row.col.f32.bf16.bf16.f32 "
        "{%0,%1,%2,%3}, {%4,%5,%6,%7}, {%8,%9}, {%0,%1,%2,%3};"
        : "+f"(c[0]), "+f"(c[1]), "+f"(c[2]), "+f"(c[3])
        : "r"(a[0]), "r"(a[1]), "r"(a[2]), "r"(a[3]), "r"(b0), "r"(b1));
}

__device__ __forceinline__ uint32_t pack_bf2(__nv_bfloat16 a, __nv_bfloat16 b) {
    uint16_t ua = *reinterpret_cast<uint16_t*>(&a);
    uint16_t ub = *reinterpret_cast<uint16_t*>(&b);
    return (uint32_t)ua | ((uint32_t)ub << 16);
}
__device__ __forceinline__ void bsplit(float x, __nv_bfloat16& h, __nv_bfloat16& l) {
    h = __float2bfloat16(x);
    l = __float2bfloat16(x - __bfloat162float(h));
}

// ======================= bf16x3 mma.sync GEMM =======================
// C[M,512] = A[M,512] @ W[512,512] (+bias; MODE1: res + relu epilogue)
// CTA 128x128, 256 thr, 8 warps (2m x 4n), warp tile 64x32, K-chunk 64.
// smem: Ah[128][64]bf16 @0, Al @16384, Bh[128n][64k] @32768, Bl @49152  = 64KB
#define GSMEM_BYTES 65536

template <int MODE>
__global__ __launch_bounds__(256) void gemm_mma(const float* __restrict__ A,
                                                const float* __restrict__ W,
                                                const float* __restrict__ bias,
                                                const float* __restrict__ res,
                                                float* __restrict__ C) {
    extern __shared__ __align__(1024) char sm[];
    const uint32_t sb = smem_u32(sm);
    const int tid = threadIdx.x, lane = tid & 31, wid = tid >> 5;
    const int wm = wid & 1, wn = wid >> 1;               // 2 x 4 warp grid
    const int mBase = blockIdx.y * 128, nBase = blockIdx.x * 128;

    const uint32_t AH = 0, AL = 16384, BH = 32768, BL = 49152;

    float acc[4][4][4];
#pragma unroll
    for (int i = 0; i < 4; i++)
#pragma unroll
        for (int j = 0; j < 4; j++)
#pragma unroll
            for (int c = 0; c < 4; c++) acc[i][j][c] = 0.f;

    // precomputed ldmatrix address components
    const uint32_t a_row = (lane & 15);
    const uint32_t a_colb = (lane >> 4) * 16;           // 0 or 16
    const uint32_t b_rowsub = ((lane >> 4) * 8) + (lane & 7);   // frag sel + row
    const uint32_t b_colb = ((lane >> 3) & 1) * 16;

    for (int kc = 0; kc < 8; kc++) {
        __syncthreads();
        // ---- load + split A chunk [128][64] ----
        {
            const float* Ab = A + (size_t)mBase * DIM_ + kc * 64;
#pragma unroll
            for (int i = 0; i < 8; i++) {
                int f = tid + i * 256;
                int r = f >> 4;
                int c4 = (f & 15) << 2;
                float4 v = *(const float4*)(Ab + (size_t)r * DIM_ + c4);
                __nv_bfloat16 hx, lx, hy, ly, hz, lz, hw, lw;
                bsplit(v.x, hx, lx); bsplit(v.y, hy, ly);
                bsplit(v.z, hz, lz); bsplit(v.w, hw, lw);
                uint32_t so = SW128((uint32_t)(r * 128 + c4 * 2));
                *(uint2*)(sm + AH + so) = make_uint2(pack_bf2(hx, hy), pack_bf2(hz, hw));
                *(uint2*)(sm + AL + so) = make_uint2(pack_bf2(lx, ly), pack_bf2(lz, lw));
            }
        }
        // ---- load + split + transpose W chunk -> B[n][k] ----
        {
            const float* Wb = W + (size_t)(kc * 64) * DIM_ + nBase;
#pragma unroll
            for (int i = 0; i < 4; i++) {
                int f = tid + i * 256;
                int k2 = f & 31;
                int n4 = ((f >> 5) & 31) << 2;
                const float* w0 = Wb + (size_t)(2 * k2) * DIM_ + n4;
                float4 r0 = *(const float4*)w0;
                float4 r1 = *(const float4*)(w0 + DIM_);
                float p0[4] = {r0.x, r0.y, r0.z, r0.w};
                float p1[4] = {r1.x, r1.y, r1.z, r1.w};
#pragma unroll
                for (int j = 0; j < 4; j++) {
                    __nv_bfloat16 h0, l0, h1, l1;
                    bsplit(p0[j], h0, l0);
                    bsplit(p1[j], h1, l1);
                    uint32_t so = SW128((uint32_t)((n4 + j) * 128 + k2 * 4));
                    *(uint32_t*)(sm + BH + so) = pack_bf2(h0, h1);
                    *(uint32_t*)(sm + BL + so) = pack_bf2(l0, l1);
                }
            }
        }
        __syncthreads();

        // ---- compute: 4 k16 steps ----
#pragma unroll
        for (int ks = 0; ks < 4; ks++) {
            uint32_t ah[4][4], al[4][4];
#pragma unroll
            for (int mf = 0; mf < 4; mf++) {
                uint32_t off = (uint32_t)((wm * 64 + mf * 16 + a_row) * 128 + ks * 32 + a_colb);
                ldsm4(ah[mf][0], ah[mf][1], ah[mf][2], ah[mf][3], sb + AH + SW128(off));
                ldsm4(al[mf][0], al[mf][1], al[mf][2], al[mf][3], sb + AL + SW128(off));
            }
#pragma unroll
            for (int j = 0; j < 4; j += 2) {
                uint32_t off = (uint32_t)((wn * 32 + j * 8 + b_rowsub) * 128 + ks * 32 + b_colb);
                uint32_t bh0, bh1, bh2, bh3, bl0, bl1, bl2, bl3;
                ldsm4(bh0, bh1, bh2, bh3, sb + BH + SW128(off));
                ldsm4(bl0, bl1, bl2, bl3, sb + BL + SW128(off));
#pragma unroll
                for (int mf = 0; mf < 4; mf++) {
                    mma_bf16(acc[mf][j],     ah[mf], bh0, bh1);
                    mma_bf16(acc[mf][j],     ah[mf], bl0, bl1);
                    mma_bf16(acc[mf][j],     al[mf], bh0, bh1);
                    mma_bf16(acc[mf][j + 1], ah[mf], bh2, bh3);
                    mma_bf16(acc[mf][j + 1], ah[mf], bl2, bl3);
                    mma_bf16(acc[mf][j + 1], al[mf], bh2, bh3);
                }
            }
        }
    }

    // ---- epilogue ----
#pragma unroll
    for (int mf = 0; mf < 4; mf++) {
        int row0 = mBase + wm * 64 + mf * 16 + (lane >> 2);
#pragma unroll
        for (int nf = 0; nf < 4; nf++) {
            int col = nBase + wn * 32 + nf * 8 + 2 * (lane & 3);
            float b0 = bias[col], b1 = bias[col + 1];
            float x0 = acc[mf][nf][0] + b0, x1 = acc[mf][nf][1] + b1;
            float x2 = acc[mf][nf][2] + b0, x3 = acc[mf][nf][3] + b1;
            float* p0 = C + (size_t)row0 * DIM_ + col;
            float* p1 = C + (size_t)(row0 + 8) * DIM_ + col;
            if (MODE == 0) {
                *(float2*)p0 = make_float2(x0, x1);
                *(float2*)p1 = make_float2(x2, x3);
            } else {
                const float* r0p = res + (size_t)row0 * DIM_ + col;
                const float* r1p = res + (size_t)(row0 + 8) * DIM_ + col;
                float2 rv0 = *(const float2*)r0p;
                float2 rv1 = *(const float2*)r1p;
                *(float2*)p0 = make_float2(rv0.x + fmaxf(x0, 0.f), rv0.y + fmaxf(x1, 0.f));
                *(float2*)p1 = make_float2(rv1.x + fmaxf(x2, 0.f), rv1.y + fmaxf(x3, 0.f));
            }
        }
    }
}

// ======================= mma.sync flash attention =======================
// grid (B*H, NQ/128). 256 thr, 8 warps; warp w owns q rows [16w,16w+16).
// Keys chunked by 64. S = Q K^T (bf16x3), online softmax on fragments,
// P fed register-to-register into PV mma (bf16x3). O = Qp + attn.
// smem 32KB: Q staging (hi@0 16K, lo@16384) then reused as
// Kh@0(8K) Kl@8192 Vh@16384 Vl@24576.
__global__ __launch_bounds__(256) void attn_mma(const float* __restrict__ Qp,
                                                const float* __restrict__ Kp,
                                                const float* __restrict__ Vp,
                                                float* __restrict__ O) {
    __shared__ __align__(1024) char sm[32768];
    const uint32_t sb = smem_u32(sm);
    const int tid = threadIdx.x, lane = tid & 31, wid = tid >> 5;
    const int bh = blockIdx.x;
    const int b = bh >> 3, h = bh & 7;
    const int q0 = blockIdx.y * 128;

    const float* Qbase = Qp + ((size_t)b * NQ_ + q0) * DIM_ + h * HD_;
    const float* Kbase = Kp + ((size_t)b * NK_) * DIM_ + h * HD_;
    const float* Vbase = Vp + ((size_t)b * NK_) * DIM_ + h * HD_;
    float* Obase = O + ((size_t)b * NQ_ + q0) * DIM_ + h * HD_;

    // ---- stage Q (scaled) as bf16 hi/lo ----
#pragma unroll
    for (int i = 0; i < 8; i++) {
        int f = tid + i * 256;
        int r = f >> 4;
        int c4 = (f & 15) << 2;
        float4 v = *(const float4*)&Qbase[(size_t)r * DIM_ + c4];
        v.x *= SCALE_; v.y *= SCALE_; v.z *= SCALE_; v.w *= SCALE_;
        __nv_bfloat16 hx, lx, hy, ly, hz, lz, hw, lw;
        bsplit(v.x, hx, lx); bsplit(v.y, hy, ly);
        bsplit(v.z, hz, lz); bsplit(v.w, hw, lw);
        uint32_t so = SW128((uint32_t)(r * 128 + c4 * 2));
        *(uint2*)(sm + so)         = make_uint2(pack_bf2(hx, hy), pack_bf2(hz, hw));
        *(uint2*)(sm + 16384 + so) = make_uint2(pack_bf2(lx, ly), pack_bf2(lz, lw));
    }
    __syncthreads();

    // ---- extract Q fragments to registers ----
    const uint32_t a_row = (lane & 15);
    const uint32_t a_colb = (lane >> 4) * 16;
    const uint32_t b_rowsub = ((lane >> 4) * 8) + (lane & 7);
    const uint32_t b_colb = ((lane >> 3) & 1) * 16;

    uint32_t qh[4][4], ql[4][4];
#pragma unroll
    for (int ks = 0; ks < 4; ks++) {
        uint32_t off = (uint32_t)((wid * 16 + a_row) * 128 + ks * 32 + a_colb);
        ldsm4(qh[ks][0], qh[ks][1], qh[ks][2], qh[ks][3], sb + SW128(off));
        ldsm4(ql[ks][0], ql[ks][1], ql[ks][2], ql[ks][3], sb + 16384 + SW128(off));
    }
    __syncthreads();   // Q staging free -> reuse for K/V

    const uint32_t KH = 0, KL = 8192, VH = 16384, VL = 24576;

    float o[8][4];
#pragma unroll
    for (int nf = 0; nf < 8; nf++)
#pragma unroll
        for (int c = 0; c < 4; c++) o[nf][c] = 0.f;
    float m0 = -1e30f, m1 = -1e30f, l0 = 0.f, l1 = 0.f;

    for (int kc = 0; kc < 16; kc++) {
        __syncthreads();
        // ---- load K chunk [64 key][64 d] hi/lo ----
#pragma unroll
        for (int i = 0; i < 4; i++) {
            int f = tid + i * 256;
            int r = f >> 4;                 // key 0..63
            int c4 = (f & 15) << 2;
            float4 v = *(const float4*)&Kbase[(size_t)(kc * 64 + r) * DIM_ + c4];
            __nv_bfloat16 hx, lx, hy, ly, hz, lz, hw, lw;
            bsplit(v.x, hx, lx); bsplit(v.y, hy, ly);
            bsplit(v.z, hz, lz); bsplit(v.w, hw, lw);
            uint32_t so = SW128((uint32_t)(r * 128 + c4 * 2));
            *(uint2*)(sm + KH + so) = make_uint2(pack_bf2(hx, hy), pack_bf2(hz, hw));
            *(uint2*)(sm + KL + so) = make_uint2(pack_bf2(lx, ly), pack_bf2(lz, lw));
        }
        // ---- load V chunk transposed -> Vst[d][key] hi/lo ----
#pragma unroll
        for (int i = 0; i < 2; i++) {
            int f = tid + i * 256;
            int k2 = f & 31;                 // key pair
            int n4 = ((f >> 5) & 15) << 2;   // d col
            const float* v0 = &Vbase[(size_t)(kc * 64 + 2 * k2) * DIM_ + n4];
            float4 r0 = *(const float4*)v0;
            float4 r1 = *(const float4*)(v0 + DIM_);
            float p0[4] = {r0.x, r0.y, r0.z, r0.w};
            float p1[4] = {r1.x, r1.y, r1.z, r1.w};
#pragma unroll
            for (int j = 0; j < 4; j++) {
                __nv_bfloat16 h0, lo0, h1, lo1;
                bsplit(p0[j], h0, lo0);
                bsplit(p1[j], h1, lo1);
                uint32_t so = SW128((uint32_t)((n4 + j) * 128 + k2 * 4));
                *(uint32_t*)(sm + VH + so) = pack_bf2(h0, h1);
                *(uint32_t*)(sm + VL + so) = pack_bf2(lo0, lo1);
            }
        }
        __syncthreads();

        // ---- S = Q K^T ----
        float s[8][4];
#pragma unroll
        for (int nf = 0; nf < 8; nf++)
#pragma unroll
            for (int c = 0; c < 4; c++) s[nf][c] = 0.f;

#pragma unroll
        for (int ks = 0; ks < 4; ks++) {
#pragma unroll
            for (int j = 0; j < 8; j += 2) {
                uint32_t off = (uint32_t)((j * 8 + b_rowsub) * 128 + ks * 32 + b_colb);
                uint32_t bh0, bh1, bh2, bh3, bl0, bl1, bl2, bl3;
                ldsm4(bh0, bh1, bh2, bh3, sb + KH + SW128(off));
                ldsm4(bl0, bl1, bl2, bl3, sb + KL + SW128(off));
                mma_bf16(s[j],     qh[ks], bh0, bh1);
                mma_bf16(s[j],     qh[ks], bl0, bl1);
                mma_bf16(s[j],     ql[ks], bh0, bh1);
                mma_bf16(s[j + 1], qh[ks], bh2, bh3);
                mma_bf16(s[j + 1], qh[ks], bl2, bl3);
                mma_bf16(s[j + 1], ql[ks], bh2, bh3);
            }
        }

        // ---- online softmax (rows lane>>2 and lane>>2+8) ----
        float mx0 = -1e30f, mx1 = -1e30f;
#pragma unroll
        for (int nf = 0; nf < 8; nf++) {
            mx0 = fmaxf(mx0, fmaxf(s[nf][0], s[nf][1]));
            mx1 = fmaxf(mx1, fmaxf(s[nf][2], s[nf][3]));
        }
        mx0 = fmaxf(mx0, __shfl_xor_sync(0xffffffffu, mx0, 1));
        mx0 = fmaxf(mx0, __shfl_xor_sync(0xffffffffu, mx0, 2));
        mx1 = fmaxf(mx1, __shfl_xor_sync(0xffffffffu, mx1, 1));
        mx1 = fmaxf(mx1, __shfl_xor_sync(0xffffffffu, mx1, 2));
        float mn0 = fmaxf(m0, mx0), mn1 = fmaxf(m1, mx1);
        float corr0 = __expf(m0 - mn0), corr1 = __expf(m1 - mn1);
        float sum0 = 0.f, sum1 = 0.f;
#pragma unroll
        for (int nf = 0; nf < 8; nf++) {
            s[nf][0] = __expf(s[nf][0] - mn0);
            s[nf][1] = __expf(s[nf][1] - mn0);
            s[nf][2] = __expf(s[nf][2] - mn1);
            s[nf][3] = __expf(s[nf][3] - mn1);
            sum0 += s[nf][0] + s[nf][1];
            sum1 += s[nf][2] + s[nf][3];
        }
        sum0 += __shfl_xor_sync(0xffffffffu, sum0, 1);
        sum0 += __shfl_xor_sync(0xffffffffu, sum0, 2);
        sum1 += __shfl_xor_sync(0xffffffffu, sum1, 1);
        sum1 += __shfl_xor_sync(0xffffffffu, sum1, 2);
        l0 = l0 * corr0 + sum0;
        l1 = l1 * corr1 + sum1;
        m0 = mn0; m1 = mn1;
#pragma unroll
        for (int nf = 0; nf < 8; nf++) {
            o[nf][0] *= corr0; o[nf][1] *= corr0;
            o[nf][2] *= corr1; o[nf][3] *= corr1;
        }

        // ---- convert P -> A fragments (hi/lo), register-only ----
        uint32_t pa_h[4][4], pa_l[4][4];
#pragma unroll
        for (int ks = 0; ks < 4; ks++) {
#pragma unroll
            for (int half = 0; half < 2; half++) {        // frag 2ks, 2ks+1
                int nf = 2 * ks + half;
                __nv_bfloat16 h0, lo0, h1, lo1, h2, lo2, h3, lo3;
                bsplit(s[nf][0], h0, lo0);
                bsplit(s[nf][1], h1, lo1);
                bsplit(s[nf][2], h2, lo2);
                bsplit(s[nf][3], h3, lo3);
                pa_h[ks][2 * half + 0] = pack_bf2(h0, h1);
                pa_h[ks][2 * half + 1] = pack_bf2(h2, h3);
                pa_l[ks][2 * half + 0] = pack_bf2(lo0, lo1);
                pa_l[ks][2 * half + 1] = pack_bf2(lo2, lo3);
            }
        }
        // NOTE: pa regs ordering: a0 = (frag 2ks rows r), a1 = (frag 2ks rows r+8),
        // a2 = (frag 2ks+1 rows r), a3 = (frag 2ks+1 rows r+8).
        // half=0 -> indices 0,1 ; half=1 -> 2,3 : matches a0..a3.

        // ---- O += P V ----
#pragma unroll
        for (int ks = 0; ks < 4; ks++) {
#pragma unroll
            for (int j = 0; j < 8; j += 2) {
                uint32_t off = (uint32_t)((j * 8 + b_rowsub) * 128 + ks * 32 + b_colb);
                uint32_t bh0, bh1, bh2, bh3, bl0, bl1, bl2, bl3;
                ldsm4(bh0, bh1, bh2, bh3, sb + VH + SW128(off));
                ldsm4(bl0, bl1, bl2, bl3, sb + VL + SW128(off));
                mma_bf16(o[j],     pa_h[ks], bh0, bh1);
                mma_bf16(o[j],     pa_h[ks], bl0, bl1);
                mma_bf16(o[j],     pa_l[ks], bh0, bh1);
                mma_bf16(o[j + 1], pa_h[ks], bh2, bh3);
                mma_bf16(o[j + 1], pa_h[ks], bl2, bl3);
                mma_bf16(o[j + 1], pa_l[ks], bh2, bh3);
            }
        }
    }

    // ---- epilogue: O = Qp + attn / l ----
    float inv0 = 1.f / l0, inv1 = 1.f / l1;
    int r0 = wid * 16 + (lane >> 2);
    int r1 = r0 + 8;
#pragma unroll
    for (int nf = 0; nf < 8; nf++) {
        int col = nf * 8 + 2 * (lane & 3);
        const float* q0p = &Qbase[(size_t)r0 * DIM_ + col];
        const float* q1p = &Qbase[(size_t)r1 * DIM_ + col];
        float2 qv0 = *(const float2*)q0p;
        float2 qv1 = *(const float2*)q1p;
        *(float2*)&Obase[(size_t)r0 * DIM_ + col] =
            make_float2(qv0.x + o[nf][0] * inv0, qv0.y + o[nf][1] * inv0);
        *(float2*)&Obase[(size_t)r1 * DIM_ + col] =
            make_float2(qv1.x + o[nf][2] * inv1, qv1.y + o[nf][3] * inv1);
    }
}

// ---------------- LayerNorm over last dim 512 (warp per row) ----------------
__global__ __launch_bounds__(256) void layernorm512(const float* __restrict__ X,
                                                    const float* __restrict__ gam,
                                                    const float* __restrict__ bet,
                                                    float* __restrict__ Y) {
    const int warp = threadIdx.x >> 5;
    const int lane = threadIdx.x & 31;
    const int row = blockIdx.x * 8 + warp;
    if (row >= MROWS) return;
    const float* x = X + (size_t)row * DIM_;
    float v[16];
    float s = 0.f, sq = 0.f;
#pragma unroll
    for (int j = 0; j < 16; j++) {
        v[j] = x[lane + j * 32];
        s += v[j];
        sq = fmaf(v[j], v[j], sq);
    }
#pragma unroll
    for (int d = 16; d > 0; d >>= 1) {
        s  += __shfl_xor_sync(0xffffffffu, s, d);
        sq += __shfl_xor_sync(0xffffffffu, sq, d);
    }
    float mean = s * (1.f / DIM_);
    float var = sq * (1.f / DIM_) - mean * mean;
    float rs = rsqrtf(var + 1e-5f);
    float* y = Y + (size_t)row * DIM_;
#pragma unroll
    for (int j = 0; j < 16; j++) {
        int col = lane + j * 32;
        y[col] = (v[j] - mean) * rs * gam[col] + bet[col];
    }
}

// ---------------- launch ----------------
extern "C" void kernel_launch(void* const* d_in, const int* in_sizes, int n_in,
                              void* d_out, int out_size) {
    const float* Q   = (const float*)d_in[0];
    const float* K   = (const float*)d_in[1];
    const float* Wq  = (const float*)d_in[2];
    const float* bq  = (const float*)d_in[3];
    const float* Wk  = (const float*)d_in[4];
    const float* bk  = (const float*)d_in[5];
    const float* Wv  = (const float*)d_in[6];
    const float* bv  = (const float*)d_in[7];
    const float* Wo  = (const float*)d_in[8];
    const float* bo  = (const float*)d_in[9];
    const float* g0  = (const float*)d_in[10];
    const float* be0 = (const float*)d_in[11];
    const float* g1  = (const float*)d_in[12];
    const float* be1 = (const float*)d_in[13];
    float* out = (float*)d_out;

    float *Qp, *Kp, *Vp, *O, *O2;
    cudaGetSymbolAddress((void**)&Qp, g_Qp);
    cudaGetSymbolAddress((void**)&Kp, g_Kp);
    cudaGetSymbolAddress((void**)&Vp, g_Vp);
    cudaGetSymbolAddress((void**)&O,  g_O);
    cudaGetSymbolAddress((void**)&O2, g_O2);

    cudaFuncSetAttribute(gemm_mma<0>, cudaFuncAttributeMaxDynamicSharedMemorySize, GSMEM_BYTES);
    cudaFuncSetAttribute(gemm_mma<1>, cudaFuncAttributeMaxDynamicSharedMemorySize, GSMEM_BYTES);

    dim3 gGrid(DIM_ / 128, MROWS / 128);   // (4, 64)

    gemm_mma<0><<<gGrid, 256, GSMEM_BYTES>>>(Q, Wq, bq, nullptr, Qp);
    gemm_mma<0><<<gGrid, 256, GSMEM_BYTES>>>(K, Wk, bk, nullptr, Kp);
    gemm_mma<0><<<gGrid, 256, GSMEM_BYTES>>>(K, Wv, bv, nullptr, Vp);

    attn_mma<<<dim3(B_ * H_, NQ_ / 128), 256>>>(Qp, Kp, Vp, O);

    layernorm512<<<MROWS / 8, 256>>>(O, g0, be0, O);

    gemm_mma<1><<<gGrid, 256, GSMEM_BYTES>>>(O, Wo, bo, O, O2);

    layernorm512<<<MROWS / 8, 256>>>(O2, g1, be1, out);
}